// round 5
// baseline (speedup 1.0000x reference)
#include <cuda_runtime.h>

#define NN   50000
#define NSEG 150000          // 3 relations x NN segments, v = r*NN + node
#define CAP  160             // bucket capacity per segment (max in-deg << 128)
#define NT   256

// ---------------- scratch (static device globals; no allocs) ----------------
__device__ int   g_is64;
__device__ int   g_dout[NSEG];           // out-degree per (r,node)
__device__ int   g_cur [NSEG];           // bucket cursors (start at v*CAP)
__device__ int   g_csr [NSEG * CAP];     // src seg id per bucket slot (96MB)
__device__ float g_h1  [NSEG * 16];      // rsqrt(dout)-scaled layer-1 features
__device__ float g_m   [NSEG * 16];      // gathered+normalized messages
__device__ float g_s   [NSEG];           // scalar layer-2 messages
__device__ float g_o2  [NSEG];           // scalar gathered layer-2

// ---------------- dtype detection ----------------
__global__ void k_detect(const unsigned* __restrict__ p, int n) {
    __shared__ int found;
    if (threadIdx.x == 0) found = 0;
    __syncthreads();
    int f = 0;
    for (int i = threadIdx.x; i < n; i += blockDim.x)
        if (p[2 * i + 1] != 0u) f = 1;
    if (f) atomicOr(&found, 1);
    __syncthreads();
    if (threadIdx.x == 0) g_is64 = found ? 0 : 1;
}

__device__ __forceinline__ int ldidx(const void* __restrict__ p, int i) {
    return g_is64 ? (int)__ldg((const long long*)p + i)
                  : __ldg((const int*)p + i);
}

__device__ __forceinline__ float rs_of(int cnt) {
    return rsqrtf((float)(cnt > 0 ? cnt : 1));
}

// ---------------- init counters/cursors ----------------
__global__ void k_zero() {
    int i = blockIdx.x * blockDim.x + threadIdx.x;
    if (i < NSEG) { g_dout[i] = 0; g_cur[i] = i * CAP; }
}

// ------- fused: out-degree count + dst-bucket fill (one pass over idx) ------
__global__ void k_degfill(const void* __restrict__ src, const void* __restrict__ dst,
                          int E, int r) {
    int e = blockIdx.x * blockDim.x + threadIdx.x;
    if (e >= E) return;
    int s = r * NN + ldidx(src, e);
    int d = r * NN + ldidx(dst, e);
    atomicAdd(&g_dout[s], 1);
    int pos = atomicAdd(&g_cur[d], 1);
    if (pos < d * CAP + CAP) g_csr[pos] = s;   // overflow prob ~1e-10; clamp for safety
}

// ---------------- layer 1: per-node transform ----------------
__global__ void k_layer1_node(const float* __restrict__ x, const float* __restrict__ W1) {
    __shared__ float sW[3 * 32 * 16];
    for (int i = threadIdx.x; i < 1536; i += blockDim.x) sW[i] = W1[i];
    __syncthreads();
    int n = blockIdx.x * blockDim.x + threadIdx.x;
    if (n >= NN) return;
    float xv[32];
    #pragma unroll
    for (int j = 0; j < 8; j++) {
        float4 v = __ldg((const float4*)(x + (size_t)n * 32) + j);
        xv[4*j] = v.x; xv[4*j+1] = v.y; xv[4*j+2] = v.z; xv[4*j+3] = v.w;
    }
    #pragma unroll
    for (int r = 0; r < 3; r++) {
        float a = rs_of(g_dout[r * NN + n]);
        float y[16];
        #pragma unroll
        for (int f = 0; f < 16; f++) y[f] = 0.f;
        #pragma unroll
        for (int j = 0; j < 32; j++) {
            float xj = xv[j];
            #pragma unroll
            for (int f = 0; f < 16; f++)
                y[f] += xj * sW[r * 512 + j * 16 + f];
        }
        float* hp = &g_h1[(size_t)(r * NN + n) * 16];
        #pragma unroll
        for (int f = 0; f < 16; f += 4)
            *(float4*)(hp + f) = make_float4(a*y[f], a*y[f+1], a*y[f+2], a*y[f+3]);
    }
}

// ---- layer 1 aggregate: warp/segment, 4 lanes/edge, 4-deep MLP, no atomics --
__global__ void k_gather16() {
    int gw = (blockIdx.x * blockDim.x + threadIdx.x) >> 5;
    int lane = threadIdx.x & 31;
    if (gw >= NSEG) return;
    int base = gw * CAP;
    int cnt  = __ldg(&g_cur[gw]) - base;
    int cl   = cnt > CAP ? CAP : cnt;
    int end  = base + cl;
    int sub = lane >> 2, c = lane & 3;
    float4 acc = make_float4(0.f, 0.f, 0.f, 0.f);
    int pos = base + sub;
    // main loop: 32 edges / warp-iter, 4 independent idx+value loads per lane
    for (; pos + 24 < end; pos += 32) {
        int s0 = __ldg(&g_csr[pos]);
        int s1 = __ldg(&g_csr[pos + 8]);
        int s2 = __ldg(&g_csr[pos + 16]);
        int s3 = __ldg(&g_csr[pos + 24]);
        float4 v0 = __ldg((const float4*)&g_h1[(size_t)s0 * 16] + c);
        float4 v1 = __ldg((const float4*)&g_h1[(size_t)s1 * 16] + c);
        float4 v2 = __ldg((const float4*)&g_h1[(size_t)s2 * 16] + c);
        float4 v3 = __ldg((const float4*)&g_h1[(size_t)s3 * 16] + c);
        acc.x += (v0.x + v1.x) + (v2.x + v3.x);
        acc.y += (v0.y + v1.y) + (v2.y + v3.y);
        acc.z += (v0.z + v1.z) + (v2.z + v3.z);
        acc.w += (v0.w + v1.w) + (v2.w + v3.w);
    }
    for (; pos < end; pos += 8) {
        int s = __ldg(&g_csr[pos]);
        float4 v = __ldg((const float4*)&g_h1[(size_t)s * 16] + c);
        acc.x += v.x; acc.y += v.y; acc.z += v.z; acc.w += v.w;
    }
    #pragma unroll
    for (int o = 4; o <= 16; o <<= 1) {
        acc.x += __shfl_xor_sync(0xffffffffu, acc.x, o);
        acc.y += __shfl_xor_sync(0xffffffffu, acc.y, o);
        acc.z += __shfl_xor_sync(0xffffffffu, acc.z, o);
        acc.w += __shfl_xor_sync(0xffffffffu, acc.w, o);
    }
    if (lane < 4) {  // lane == c, sub == 0
        float ain = rs_of(cnt);
        *(float4*)&g_m[(size_t)gw * 16 + lane * 4] =
            make_float4(acc.x * ain, acc.y * ain, acc.z * ain, acc.w * ain);
    }
}

// ---------------- combine + relu + layer-2 node transform ----------------
__global__ void k_combine(const float* __restrict__ b1, const float* __restrict__ W2) {
    __shared__ float sW2[48], sb1[48];
    if (threadIdx.x < 48) {
        sW2[threadIdx.x] = W2[threadIdx.x];
        sb1[threadIdx.x] = b1[threadIdx.x];
    }
    __syncthreads();
    int n = blockIdx.x * blockDim.x + threadIdx.x;
    if (n >= NN) return;
    float acc[16];
    #pragma unroll
    for (int f = 0; f < 16; f++) acc[f] = 0.f;
    #pragma unroll
    for (int r = 0; r < 3; r++) {
        const float* mp = &g_m[(size_t)(r * NN + n) * 16];
        #pragma unroll
        for (int f = 0; f < 16; f += 4) {
            float4 v = *(const float4*)(mp + f);
            acc[f]   += v.x + sb1[r*16 + f];
            acc[f+1] += v.y + sb1[r*16 + f + 1];
            acc[f+2] += v.z + sb1[r*16 + f + 2];
            acc[f+3] += v.w + sb1[r*16 + f + 3];
        }
    }
    #pragma unroll
    for (int f = 0; f < 16; f++) acc[f] = fmaxf(acc[f], 0.f);
    #pragma unroll
    for (int r = 0; r < 3; r++) {
        float aout = rs_of(g_dout[r * NN + n]);
        float dot = 0.f;
        #pragma unroll
        for (int f = 0; f < 16; f++) dot += acc[f] * sW2[r*16 + f];
        g_s[r * NN + n] = aout * dot;
    }
}

// ---------------- layer 2 aggregate: warp per segment, MLP-4 ----------------
__global__ void k_gather1() {
    int gw = (blockIdx.x * blockDim.x + threadIdx.x) >> 5;
    int lane = threadIdx.x & 31;
    if (gw >= NSEG) return;
    int base = gw * CAP;
    int cnt  = __ldg(&g_cur[gw]) - base;
    int cl   = cnt > CAP ? CAP : cnt;
    int end  = base + cl;
    float acc = 0.f;
    int pos = base + lane;
    for (; pos + 96 < end; pos += 128) {
        int s0 = __ldg(&g_csr[pos]);
        int s1 = __ldg(&g_csr[pos + 32]);
        int s2 = __ldg(&g_csr[pos + 64]);
        int s3 = __ldg(&g_csr[pos + 96]);
        acc += (__ldg(&g_s[s0]) + __ldg(&g_s[s1])) + (__ldg(&g_s[s2]) + __ldg(&g_s[s3]));
    }
    for (; pos < end; pos += 32)
        acc += __ldg(&g_s[__ldg(&g_csr[pos])]);
    #pragma unroll
    for (int o = 16; o; o >>= 1) acc += __shfl_xor_sync(0xffffffffu, acc, o);
    if (lane == 0)
        g_o2[gw] = acc * rs_of(cnt);
}

// ---------------- final ----------------
__global__ void k_final(float* __restrict__ out, const float* __restrict__ b2) {
    int n = blockIdx.x * blockDim.x + threadIdx.x;
    if (n >= NN) return;
    float o = __ldg(b2) + __ldg(b2 + 1) + __ldg(b2 + 2);
    #pragma unroll
    for (int r = 0; r < 3; r++)
        o += g_o2[r * NN + n];
    out[n] = o;
}

// ---------------- host ----------------
extern "C" void kernel_launch(void* const* d_in, const int* in_sizes, int n_in,
                              void* d_out, int out_size) {
    const float* x  = (const float*)d_in[0];
    const void*  src[3] = { d_in[1], d_in[3], d_in[5] };
    const void*  dst[3] = { d_in[2], d_in[4], d_in[6] };
    int          E[3]   = { in_sizes[1], in_sizes[3], in_sizes[5] };
    const float* W1 = (const float*)d_in[7];
    const float* b1 = (const float*)d_in[8];
    const float* W2 = (const float*)d_in[9];
    const float* b2 = (const float*)d_in[10];
    float*       out = (float*)d_out;

    int nprobe = E[0] < 2048 ? E[0] : 2048;
    k_detect<<<1, NT>>>((const unsigned*)d_in[1], nprobe);

    k_zero<<<(NSEG + NT - 1) / NT, NT>>>();
    for (int r = 0; r < 3; r++)
        k_degfill<<<(E[r] + NT - 1) / NT, NT>>>(src[r], dst[r], E[r], r);

    k_layer1_node<<<(NN + NT - 1) / NT, NT>>>(x, W1);

    long long thr = (long long)NSEG * 32;
    k_gather16<<<(int)((thr + NT - 1) / NT), NT>>>();

    k_combine<<<(NN + NT - 1) / NT, NT>>>(b1, W2);
    k_gather1<<<(int)((thr + NT - 1) / NT), NT>>>();

    k_final<<<(NN + NT - 1) / NT, NT>>>(out, b2);
}